// round 3
// baseline (speedup 1.0000x reference)
#include <cuda_runtime.h>
#include <cuda_bf16.h>

#define HH 1024
#define WW 2048
#define HWSZ (HH * WW)
#define NC 19
#define RAD 16
#define INV_LOG19 0.3396224f   // 1 / ln(19)

// -------- scratch (device globals: allocation-free per harness rules) -------
__device__ unsigned char g_predict[HWSZ];   // argmax class per pixel
__device__ float         g_wpe[HWSZ];       // weighted pixel entropy / ln19
// SoA 24B/pixel vertical-window records: perfectly coalesced 8B-stride access
__device__ uint2 g_r0[HWSZ];   // classes 0..7   (4x u16 lanes x2)
__device__ uint2 g_r1[HWSZ];   // classes 8..15
__device__ uint2 g_r2[HWSZ];   // classes 16..18 + pad | vertical entropy sum

// ============================================================================
// Pass A: per-pixel softmax entropy + argmax + weighted entropy
// ============================================================================
__global__ __launch_bounds__(256) void passA(const float* __restrict__ logit,
                                             const float* __restrict__ cw) {
    int i = blockIdx.x * blockDim.x + threadIdx.x;
    if (i >= HWSZ) return;

    float v[NC];
#pragma unroll
    for (int c = 0; c < NC; c++) v[c] = logit[c * HWSZ + i];

    float m = v[0];
    int am = 0;
#pragma unroll
    for (int c = 1; c < NC; c++) {
        if (v[c] > m) { m = v[c]; am = c; }
    }

    float S = 0.f, T = 0.f;
#pragma unroll
    for (int c = 0; c < NC; c++) {
        float d = v[c] - m;
        float e = __expf(d);
        S += e;
        T += e * d;
    }
    float ent = __logf(S) - T * __frcp_rn(S);

    g_predict[i] = (unsigned char)am;
    g_wpe[i] = ent * cw[am] * INV_LOG19;
}

// ============================================================================
// Pass B: vertical 33-tap box filter -> SoA records (coalesced STG.64)
// ============================================================================
#define CHB 16

__device__ __forceinline__ void pk_add(unsigned long long& w0,
                                       unsigned long long& w1,
                                       unsigned long long& w2, int cls) {
    unsigned long long inc = 1ull << ((cls & 7) * 8);
    if (cls < 8)       w0 += inc;
    else if (cls < 16) w1 += inc;
    else               w2 += inc;
}
__device__ __forceinline__ void pk_sub(unsigned long long& w0,
                                       unsigned long long& w1,
                                       unsigned long long& w2, int cls) {
    unsigned long long dec = 1ull << ((cls & 7) * 8);
    if (cls < 8)       w0 -= dec;
    else if (cls < 16) w1 -= dec;
    else               w2 -= dec;
}

__global__ __launch_bounds__(256) void passB() {
    int x  = blockIdx.x * blockDim.x + threadIdx.x;   // column (lane-consecutive)
    int y0 = blockIdx.y * CHB;

    unsigned long long w0 = 0, w1 = 0, w2 = 0;
    float fs = 0.f;

    int ys = y0 - RAD; if (ys < 0) ys = 0;
    int ye = y0 + RAD; if (ye > HH - 1) ye = HH - 1;
    for (int y = ys; y <= ye; ++y) {
        int idx = y * WW + x;
        fs += g_wpe[idx];
        pk_add(w0, w1, w2, g_predict[idx]);
    }

#pragma unroll 4
    for (int k = 0; k < CHB; k++) {
        int y = y0 + k;
        int idx = y * WW + x;

        g_r0[idx] = make_uint2((unsigned)w0, (unsigned)(w0 >> 32));
        g_r1[idx] = make_uint2((unsigned)w1, (unsigned)(w1 >> 32));
        g_r2[idx] = make_uint2((unsigned)w2, __float_as_uint(fs));

        int ya = y + RAD + 1;
        if (ya < HH) {
            int ia = ya * WW + x;
            fs += g_wpe[ia];
            pk_add(w0, w1, w2, g_predict[ia]);
        }
        int yr = y - RAD;
        if (yr >= 0) {
            int ir = yr * WW + x;
            fs -= g_wpe[ir];
            pk_sub(w0, w1, w2, g_predict[ir]);
        }
    }
}

// ============================================================================
// Pass C: horizontal 33-tap box filter via SIMD 16-bit-lane sliding sums.
// No MUFU in the hot loop: smem LUT g(n) = n*ln(n); impurity computed as
//   ((g(count) - sum g(s)) * invc - K*1e-6) / ln19
// which matches the reference's -sum d*log(d+1e-6) to ~1e-8 absolute.
// ============================================================================
#define CHC 16
#define NCHK (WW / CHC)   // 128 chunks per row
#define LUTN 1090         // counts range 0..33*33

// unpack 4 bytes of w into two u32 halfword pairs
#define PLO(w) __byte_perm((w), 0, 0x4140)
#define PHI(w) __byte_perm((w), 0, 0x4342)

__device__ __forceinline__ void rec_add(unsigned* h, float& fs, int idx) {
    uint2 a = g_r0[idx];
    uint2 b = g_r1[idx];
    uint2 c = g_r2[idx];
    h[0] += PLO(a.x); h[1] += PHI(a.x);
    h[2] += PLO(a.y); h[3] += PHI(a.y);
    h[4] += PLO(b.x); h[5] += PHI(b.x);
    h[6] += PLO(b.y); h[7] += PHI(b.y);
    h[8] += PLO(c.x); h[9] += PHI(c.x);   // classes 16..18 (+zero pad)
    fs += __uint_as_float(c.y);
}
__device__ __forceinline__ void rec_sub(unsigned* h, float& fs, int idx) {
    uint2 a = g_r0[idx];
    uint2 b = g_r1[idx];
    uint2 c = g_r2[idx];
    h[0] -= PLO(a.x); h[1] -= PHI(a.x);
    h[2] -= PLO(a.y); h[3] -= PHI(a.y);
    h[4] -= PLO(b.x); h[5] -= PHI(b.x);
    h[6] -= PLO(b.y); h[7] -= PHI(b.y);
    h[8] -= PLO(c.x); h[9] -= PHI(c.x);
    fs -= __uint_as_float(c.y);
}

__global__ __launch_bounds__(256) void passC(float* __restrict__ out) {
    __shared__ float lutg[LUTN];
    for (int n = threadIdx.x; n < LUTN; n += 256)
        lutg[n] = (n == 0) ? 0.f : (float)n * __logf((float)n);
    __syncthreads();

    int tid = blockIdx.x * blockDim.x + threadIdx.x;
    int j = tid & (NCHK - 1);
    int y = tid >> 7;               // NCHK = 128
    if (y >= HH) return;
    int x0 = j * CHC;
    int rowbase = y * WW;

    unsigned h[10];
#pragma unroll
    for (int i = 0; i < 10; i++) h[i] = 0;
    float fs = 0.f;

    int xs = x0 - RAD; if (xs < 0) xs = 0;
    int xe = x0 + RAD; if (xe > WW - 1) xe = WW - 1;
    for (int x = xs; x <= xe; ++x) rec_add(h, fs, rowbase + x);

#pragma unroll 1
    for (int k4 = 0; k4 < CHC / 4; k4++) {
        float s4[4], i4[4], u4[4];
#pragma unroll
        for (int kk = 0; kk < 4; kk++) {
            int x = x0 + k4 * 4 + kk;

            // count = sum of all 16-bit lanes (fold: total <= 20691 < 2^16)
            unsigned t = h[0] + h[1] + h[2] + h[3] + h[4]
                       + h[5] + h[6] + h[7] + h[8] + h[9];
            unsigned count = (t & 0xFFFFu) + (t >> 16);
            float fcount = (float)count;
            float invc = __frcp_rn(fcount);

            float acc = 0.f;
            int K = 0;
#pragma unroll
            for (int p = 0; p < 10; p++) {
                unsigned slo = h[p] & 0xFFFFu;
                unsigned shi = h[p] >> 16;
                acc += lutg[slo] + lutg[shi];
                K += (slo != 0) + (shi != 0);
            }
            float impurity = ((lutg[count] - acc) * invc - (float)K * 1e-6f)
                             * INV_LOG19;
            float unc = fs * invc;

            s4[kk] = impurity * unc;
            i4[kk] = impurity;
            u4[kk] = unc;

            int xa = x + RAD + 1;
            if (xa < WW) rec_add(h, fs, rowbase + xa);
            int xr = x - RAD;
            if (xr >= 0) rec_sub(h, fs, rowbase + xr);
        }
        int o = rowbase + x0 + k4 * 4;
        *(float4*)(out + o)             = make_float4(s4[0], s4[1], s4[2], s4[3]);
        *(float4*)(out + HWSZ + o)      = make_float4(i4[0], i4[1], i4[2], i4[3]);
        *(float4*)(out + 2 * HWSZ + o)  = make_float4(u4[0], u4[1], u4[2], u4[3]);
    }
}

// ============================================================================
extern "C" void kernel_launch(void* const* d_in, const int* in_sizes, int n_in,
                              void* d_out, int out_size) {
    const float* logit = (const float*)d_in[0];
    const float* cw    = (const float*)d_in[1];
    float* out = (float*)d_out;

    passA<<<HWSZ / 256, 256>>>(logit, cw);
    {
        dim3 grid(WW / 256, HH / CHB);
        passB<<<grid, 256>>>();
    }
    passC<<<(HH * NCHK) / 256, 256>>>(out);
}

// round 4
// speedup vs baseline: 1.2938x; 1.2938x over previous
#include <cuda_runtime.h>
#include <cuda_bf16.h>

#define HH 1024
#define WW 2048
#define HWSZ (HH * WW)
#define NC 19
#define RAD 16
#define INV_LOG19 0.3396224f   // 1 / ln(19)

// -------- scratch (device globals: allocation-free per harness rules) -------
__device__ unsigned char g_predict[HWSZ];   // argmax class per pixel
__device__ float         g_wpe[HWSZ];       // weighted pixel entropy / ln19

// ============================================================================
// Pass A: per-pixel softmax entropy + argmax + weighted entropy  (unchanged,
// measured 72% DRAM roofline)
// ============================================================================
__global__ __launch_bounds__(256) void passA(const float* __restrict__ logit,
                                             const float* __restrict__ cw) {
    int i = blockIdx.x * blockDim.x + threadIdx.x;
    if (i >= HWSZ) return;

    float v[NC];
#pragma unroll
    for (int c = 0; c < NC; c++) v[c] = logit[c * HWSZ + i];

    float m = v[0];
    int am = 0;
#pragma unroll
    for (int c = 1; c < NC; c++) {
        if (v[c] > m) { m = v[c]; am = c; }
    }

    float S = 0.f, T = 0.f;
#pragma unroll
    for (int c = 0; c < NC; c++) {
        float d = v[c] - m;
        float e = __expf(d);
        S += e;
        T += e * d;
    }
    float ent = __logf(S) - T * __frcp_rn(S);

    g_predict[i] = (unsigned char)am;
    g_wpe[i] = ent * cw[am] * INV_LOG19;
}

// ============================================================================
// Fused passBC: vertical slide -> smem records -> horizontal slide -> outputs.
// Tile: 128 output cols x 16 output rows per block (grid 16 x 64).
// ============================================================================
#define W_OUT 128
#define W_IN  160            // + 2*RAD halo columns
#define HB    16             // output rows per block
#define CHC_F 8              // outputs per horizontal-slider task
#define ROWSTRIDE 1284       // words per record-row: 160*8 + 4 pad (bank layout)
#define SMEM_WORDS (HB * ROWSTRIDE)
#define SMEM_BYTES (SMEM_WORDS * 4)

__device__ __forceinline__ void pk_add(unsigned long long& w0,
                                       unsigned long long& w1,
                                       unsigned long long& w2, int cls) {
    unsigned long long inc = 1ull << ((cls & 7) * 8);
    if (cls < 8)       w0 += inc;
    else if (cls < 16) w1 += inc;
    else               w2 += inc;
}
__device__ __forceinline__ void pk_sub(unsigned long long& w0,
                                       unsigned long long& w1,
                                       unsigned long long& w2, int cls) {
    unsigned long long dec = 1ull << ((cls & 7) * 8);
    if (cls < 8)       w0 -= dec;
    else if (cls < 16) w1 -= dec;
    else               w2 -= dec;
}

// unpack 4 bytes into two u32 halfword pairs
#define PLO(w) __byte_perm((w), 0, 0x4140)
#define PHI(w) __byte_perm((w), 0, 0x4342)

__device__ __forceinline__ void srec_add(const unsigned* __restrict__ sm,
                                         int r, int s, unsigned* h, float& fs) {
    const unsigned* rec = sm + r * ROWSTRIDE + s * 8;
    uint4 a = *(const uint4*)rec;        // w0.lo, w0.hi, w1.lo, w1.hi
    uint4 b = *(const uint4*)(rec + 4);  // w2.lo, w2.hi, fs, 0
    h[0] += PLO(a.x); h[1] += PHI(a.x);
    h[2] += PLO(a.y); h[3] += PHI(a.y);
    h[4] += PLO(a.z); h[5] += PHI(a.z);
    h[6] += PLO(a.w); h[7] += PHI(a.w);
    h[8] += PLO(b.x); h[9] += PHI(b.x);
    fs += __uint_as_float(b.z);
}
__device__ __forceinline__ void srec_sub(const unsigned* __restrict__ sm,
                                         int r, int s, unsigned* h, float& fs) {
    const unsigned* rec = sm + r * ROWSTRIDE + s * 8;
    uint4 a = *(const uint4*)rec;
    uint4 b = *(const uint4*)(rec + 4);
    h[0] -= PLO(a.x); h[1] -= PHI(a.x);
    h[2] -= PLO(a.y); h[3] -= PHI(a.y);
    h[4] -= PLO(a.z); h[5] -= PHI(a.z);
    h[6] -= PLO(a.w); h[7] -= PHI(a.w);
    h[8] -= PLO(b.x); h[9] -= PHI(b.x);
    fs -= __uint_as_float(b.z);
}

__global__ __launch_bounds__(256) void fusedBC(float* __restrict__ out) {
    extern __shared__ unsigned sm[];
    const int x0 = blockIdx.x * W_OUT;
    const int y0 = blockIdx.y * HB;
    const int tid = threadIdx.x;

    // ---------------- Phase 1: vertical 33-tap sliders (160 threads) --------
    if (tid < W_IN) {
        int xg = x0 - RAD + tid;
        if (xg < 0) xg = 0;                 // edge blocks: clamped column; its
        if (xg > WW - 1) xg = WW - 1;       // records are never read by phase 2

        unsigned long long w0 = 0, w1 = 0, w2 = 0;
        float fs = 0.f;
#pragma unroll
        for (int yi = 0; yi < 33; yi++) {
            int y = y0 - RAD + yi;
            if (y >= 0 && y < HH) {
                int idx = y * WW + xg;
                fs += g_wpe[idx];
                pk_add(w0, w1, w2, g_predict[idx]);
            }
        }
#pragma unroll 4
        for (int r = 0; r < HB; r++) {
            unsigned* rec = sm + r * ROWSTRIDE + tid * 8;
            *(uint4*)rec       = make_uint4((unsigned)w0, (unsigned)(w0 >> 32),
                                            (unsigned)w1, (unsigned)(w1 >> 32));
            *(uint4*)(rec + 4) = make_uint4((unsigned)w2, (unsigned)(w2 >> 32),
                                            __float_as_uint(fs), 0u);
            int ya = y0 + r + RAD + 1;
            if (ya < HH) {
                int ia = ya * WW + xg;
                fs += g_wpe[ia];
                pk_add(w0, w1, w2, g_predict[ia]);
            }
            int yr = y0 + r - RAD;
            if (yr >= 0) {
                int ir = yr * WW + xg;
                fs -= g_wpe[ir];
                pk_sub(w0, w1, w2, g_predict[ir]);
            }
        }
    }
    __syncthreads();

    // ---------------- Phase 2: horizontal 33-tap sliders (256 tasks) --------
    // t = c*16 + r  -> 8-lane LDS phases differ only in r: conflict-free.
    const int c = tid >> 4;
    const int r = tid & 15;
    const int xo = x0 + c * CHC_F;

    unsigned h[10];
#pragma unroll
    for (int i = 0; i < 10; i++) h[i] = 0;
    float fs = 0.f;

#pragma unroll
    for (int si = 0; si < 33; si++) {
        int xg = xo - RAD + si;
        if (xg >= 0 && xg < WW) srec_add(sm, r, c * CHC_F + si, h, fs);
    }

    float s4[CHC_F], i4[CHC_F], u4[CHC_F];
#pragma unroll
    for (int k = 0; k < CHC_F; k++) {
        // count = sum of all 16-bit lanes (fold: total <= 1089 < 2^16)
        unsigned t = h[0] + h[1] + h[2] + h[3] + h[4]
                   + h[5] + h[6] + h[7] + h[8] + h[9];
        unsigned count = (t & 0xFFFFu) + (t >> 16);
        float fcount = (float)count;
        float invc = __frcp_rn(fcount);
        float eps = 1e-6f * fcount;

        float acc = 0.f;
#pragma unroll
        for (int p = 0; p < 10; p++) {
            float slo = (float)(h[p] & 0xFFFFu);
            float shi = (float)(h[p] >> 16);
            acc += slo * __logf(slo + eps);   // 0*log(eps) == 0
            if (p != 9)                        // lane 19 is zero pad
                acc += shi * __logf(shi + eps);
        }
        float impurity = (__logf(fcount) - acc * invc) * INV_LOG19;
        float unc = fs * invc;

        s4[k] = impurity * unc;
        i4[k] = impurity;
        u4[k] = unc;

        if (k < CHC_F - 1) {
            int xa = xo + k + RAD + 1;
            if (xa < WW) srec_add(sm, r, c * CHC_F + k + 33, h, fs);
            int xr = xo + k - RAD;
            if (xr >= 0) srec_sub(sm, r, c * CHC_F + k, h, fs);
        }
    }

    int o = (y0 + r) * WW + xo;
    *(float4*)(out + o)                = make_float4(s4[0], s4[1], s4[2], s4[3]);
    *(float4*)(out + o + 4)            = make_float4(s4[4], s4[5], s4[6], s4[7]);
    *(float4*)(out + HWSZ + o)         = make_float4(i4[0], i4[1], i4[2], i4[3]);
    *(float4*)(out + HWSZ + o + 4)     = make_float4(i4[4], i4[5], i4[6], i4[7]);
    *(float4*)(out + 2 * HWSZ + o)     = make_float4(u4[0], u4[1], u4[2], u4[3]);
    *(float4*)(out + 2 * HWSZ + o + 4) = make_float4(u4[4], u4[5], u4[6], u4[7]);
}

// ============================================================================
extern "C" void kernel_launch(void* const* d_in, const int* in_sizes, int n_in,
                              void* d_out, int out_size) {
    const float* logit = (const float*)d_in[0];
    const float* cw    = (const float*)d_in[1];
    float* out = (float*)d_out;

    cudaFuncSetAttribute(fusedBC, cudaFuncAttributeMaxDynamicSharedMemorySize,
                         SMEM_BYTES);

    passA<<<HWSZ / 256, 256>>>(logit, cw);
    fusedBC<<<dim3(WW / W_OUT, HH / HB), 256, SMEM_BYTES>>>(out);
}

// round 5
// speedup vs baseline: 1.3096x; 1.0123x over previous
#include <cuda_runtime.h>
#include <cuda_bf16.h>

#define HH 1024
#define WW 2048
#define HWSZ (HH * WW)
#define NC 19
#define RAD 16
#define INV_LOG19 0.3396224f   // 1 / ln(19)

// -------- scratch (device globals: allocation-free per harness rules) -------
__device__ unsigned char g_predict[HWSZ];   // argmax class per pixel
__device__ float         g_wpe[HWSZ];       // weighted pixel entropy / ln19

// ============================================================================
// Pass A: per-pixel softmax entropy + argmax + weighted entropy  (unchanged,
// measured 72% DRAM roofline)
// ============================================================================
__global__ __launch_bounds__(256) void passA(const float* __restrict__ logit,
                                             const float* __restrict__ cw) {
    int i = blockIdx.x * blockDim.x + threadIdx.x;
    if (i >= HWSZ) return;

    float v[NC];
#pragma unroll
    for (int c = 0; c < NC; c++) v[c] = logit[c * HWSZ + i];

    float m = v[0];
    int am = 0;
#pragma unroll
    for (int c = 1; c < NC; c++) {
        if (v[c] > m) { m = v[c]; am = c; }
    }

    float S = 0.f, T = 0.f;
#pragma unroll
    for (int c = 0; c < NC; c++) {
        float d = v[c] - m;
        float e = __expf(d);
        S += e;
        T += e * d;
    }
    float ent = __logf(S) - T * __frcp_rn(S);

    g_predict[i] = (unsigned char)am;
    g_wpe[i] = ent * cw[am] * INV_LOG19;
}

// ============================================================================
// Fused passBC: vertical slide -> smem records -> horizontal slide -> outputs.
// Tile: 256 output cols x 8 output rows. Grid (8, 128) = 1024 blocks.
// smem 73.9KB -> 3 blocks/SM, all 256 threads active in both phases.
// ============================================================================
#define W_OUT 256
#define W_IN  288            // + 2*RAD halo columns
#define HB    8              // output rows per block
#define CHC_F 8              // outputs per horizontal-slider task
#define NCHUNK 32            // chunks per row (32*8 = 256 cols)
#define ROWSTRIDE (W_IN * 8 + 4)   // 2308 words; 2308 % 32 == 4 -> r*4 distinct
#define SMEM_WORDS (HB * ROWSTRIDE)
#define SMEM_BYTES (SMEM_WORDS * 4)

__device__ __forceinline__ void pk_add(unsigned long long& w0,
                                       unsigned long long& w1,
                                       unsigned long long& w2, int cls) {
    unsigned long long inc = 1ull << ((cls & 7) * 8);
    if (cls < 8)       w0 += inc;
    else if (cls < 16) w1 += inc;
    else               w2 += inc;
}
__device__ __forceinline__ void pk_sub(unsigned long long& w0,
                                       unsigned long long& w1,
                                       unsigned long long& w2, int cls) {
    unsigned long long dec = 1ull << ((cls & 7) * 8);
    if (cls < 8)       w0 -= dec;
    else if (cls < 16) w1 -= dec;
    else               w2 -= dec;
}

// unpack 4 bytes into two u32 halfword pairs
#define PLO(w) __byte_perm((w), 0, 0x4140)
#define PHI(w) __byte_perm((w), 0, 0x4342)

__device__ __forceinline__ void srec_add(const unsigned* __restrict__ rec,
                                         unsigned* h, float& fs) {
    uint4 a = *(const uint4*)rec;        // w0.lo, w0.hi, w1.lo, w1.hi
    uint4 b = *(const uint4*)(rec + 4);  // w2.lo, w2.hi, fs, 0
    h[0] += PLO(a.x); h[1] += PHI(a.x);
    h[2] += PLO(a.y); h[3] += PHI(a.y);
    h[4] += PLO(a.z); h[5] += PHI(a.z);
    h[6] += PLO(a.w); h[7] += PHI(a.w);
    h[8] += PLO(b.x); h[9] += PHI(b.x);
    fs += __uint_as_float(b.z);
}
__device__ __forceinline__ void srec_sub(const unsigned* __restrict__ rec,
                                         unsigned* h, float& fs) {
    uint4 a = *(const uint4*)rec;
    uint4 b = *(const uint4*)(rec + 4);
    h[0] -= PLO(a.x); h[1] -= PHI(a.x);
    h[2] -= PLO(a.y); h[3] -= PHI(a.y);
    h[4] -= PLO(a.z); h[5] -= PHI(a.z);
    h[6] -= PLO(a.w); h[7] -= PHI(a.w);
    h[8] -= PLO(b.x); h[9] -= PHI(b.x);
    fs -= __uint_as_float(b.z);
}

__global__ __launch_bounds__(256, 3) void fusedBC(float* __restrict__ out) {
    extern __shared__ unsigned sm[];
    const int x0 = blockIdx.x * W_OUT;
    const int y0 = blockIdx.y * HB;
    const int tid = threadIdx.x;

    // ---------------- Phase 1: vertical 33-tap sliders (288 cols, strided) --
    for (int j = tid; j < W_IN; j += 256) {
        int xg = x0 - RAD + j;
        bool valid = (xg >= 0) && (xg < WW);

        unsigned long long w0 = 0, w1 = 0, w2 = 0;
        float fs = 0.f;
        if (valid) {
#pragma unroll
            for (int yi = 0; yi < 33; yi++) {
                int y = y0 - RAD + yi;
                if (y >= 0 && y < HH) {
                    int idx = y * WW + xg;
                    fs += g_wpe[idx];
                    pk_add(w0, w1, w2, g_predict[idx]);
                }
            }
        }
#pragma unroll
        for (int r = 0; r < HB; r++) {
            unsigned* rec = sm + r * ROWSTRIDE + j * 8;
            *(uint4*)rec       = make_uint4((unsigned)w0, (unsigned)(w0 >> 32),
                                            (unsigned)w1, (unsigned)(w1 >> 32));
            *(uint4*)(rec + 4) = make_uint4((unsigned)w2, (unsigned)(w2 >> 32),
                                            __float_as_uint(fs), 0u);
            if (valid) {
                int ya = y0 + r + RAD + 1;
                if (ya < HH) {
                    int ia = ya * WW + xg;
                    fs += g_wpe[ia];
                    pk_add(w0, w1, w2, g_predict[ia]);
                }
                int yr = y0 + r - RAD;
                if (yr >= 0) {
                    int ir = yr * WW + xg;
                    fs -= g_wpe[ir];
                    pk_sub(w0, w1, w2, g_predict[ir]);
                }
            }
        }
    }
    __syncthreads();

    // ---------------- Phase 2: horizontal 33-tap sliders (256 tasks) --------
    // r in low 3 bits: the 8 lanes of each LDS.128 phase hit distinct banks
    // (ROWSTRIDE % 32 == 4 -> r*4 mod 32 all distinct).
    const int r = tid & 7;
    const int c = tid >> 3;
    const int xo = x0 + c * CHC_F;
    const unsigned* smrow = sm + r * ROWSTRIDE;

    // vertical window height for this output row (closed form)
    int yy = y0 + r;
    int wy = min(yy + RAD, HH - 1) - max(yy - RAD, 0) + 1;

    unsigned h[10];
#pragma unroll
    for (int i = 0; i < 10; i++) h[i] = 0;
    float fs = 0.f;

#pragma unroll
    for (int si = 0; si < 33; si++)
        srec_add(smrow + (c * CHC_F + si) * 8, h, fs);

    float s4[CHC_F], i4[CHC_F], u4[CHC_F];
#pragma unroll
    for (int k = 0; k < CHC_F; k++) {
        int x = xo + k;
        int wx = min(x + RAD, WW - 1) - max(x - RAD, 0) + 1;
        float fcount = (float)(wx * wy);     // exact: equals sum of all lanes
        float invc = __frcp_rn(fcount);
        float eps = 1e-6f * fcount;

        float acc = 0.f;
#pragma unroll
        for (int p = 0; p < 10; p++) {
            float slo = (float)(h[p] & 0xFFFFu);
            float shi = (float)(h[p] >> 16);
            acc += slo * __logf(slo + eps);   // 0*log(eps) == 0
            if (p != 9)                        // lane 19 is zero pad
                acc += shi * __logf(shi + eps);
        }
        float impurity = (__logf(fcount) - acc * invc) * INV_LOG19;
        float unc = fs * invc;

        s4[k] = impurity * unc;
        i4[k] = impurity;
        u4[k] = unc;

        if (k < CHC_F - 1) {
            srec_add(smrow + (c * CHC_F + k + 33) * 8, h, fs);
            srec_sub(smrow + (c * CHC_F + k) * 8, h, fs);
        }
    }

    int o = yy * WW + xo;
    *(float4*)(out + o)                = make_float4(s4[0], s4[1], s4[2], s4[3]);
    *(float4*)(out + o + 4)            = make_float4(s4[4], s4[5], s4[6], s4[7]);
    *(float4*)(out + HWSZ + o)         = make_float4(i4[0], i4[1], i4[2], i4[3]);
    *(float4*)(out + HWSZ + o + 4)     = make_float4(i4[4], i4[5], i4[6], i4[7]);
    *(float4*)(out + 2 * HWSZ + o)     = make_float4(u4[0], u4[1], u4[2], u4[3]);
    *(float4*)(out + 2 * HWSZ + o + 4) = make_float4(u4[4], u4[5], u4[6], u4[7]);
}

// ============================================================================
extern "C" void kernel_launch(void* const* d_in, const int* in_sizes, int n_in,
                              void* d_out, int out_size) {
    const float* logit = (const float*)d_in[0];
    const float* cw    = (const float*)d_in[1];
    float* out = (float*)d_out;

    cudaFuncSetAttribute(fusedBC, cudaFuncAttributeMaxDynamicSharedMemorySize,
                         SMEM_BYTES);

    passA<<<HWSZ / 256, 256>>>(logit, cw);
    fusedBC<<<dim3(WW / W_OUT, HH / HB), 256, SMEM_BYTES>>>(out);
}

// round 6
// speedup vs baseline: 1.5436x; 1.1787x over previous
#include <cuda_runtime.h>
#include <cuda_bf16.h>

#define HH 1024
#define WW 2048
#define HWSZ (HH * WW)
#define NC 19
#define RAD 16
#define INV_LOG19 0.3396224f   // 1 / ln(19)

// -------- scratch (device globals: allocation-free per harness rules) -------
__device__ unsigned char g_predict[HWSZ];   // argmax class per pixel
__device__ float         g_wpe[HWSZ];       // weighted pixel entropy / ln19

// ============================================================================
// Pass A: per-pixel softmax entropy + argmax + weighted entropy  (unchanged,
// measured 72% DRAM roofline)
// ============================================================================
__global__ __launch_bounds__(256) void passA(const float* __restrict__ logit,
                                             const float* __restrict__ cw) {
    int i = blockIdx.x * blockDim.x + threadIdx.x;
    if (i >= HWSZ) return;

    float v[NC];
#pragma unroll
    for (int c = 0; c < NC; c++) v[c] = logit[c * HWSZ + i];

    float m = v[0];
    int am = 0;
#pragma unroll
    for (int c = 1; c < NC; c++) {
        if (v[c] > m) { m = v[c]; am = c; }
    }

    float S = 0.f, T = 0.f;
#pragma unroll
    for (int c = 0; c < NC; c++) {
        float d = v[c] - m;
        float e = __expf(d);
        S += e;
        T += e * d;
    }
    float ent = __logf(S) - T * __frcp_rn(S);

    g_predict[i] = (unsigned char)am;
    g_wpe[i] = ent * cw[am] * INV_LOG19;
}

// ============================================================================
// Fused passBC. Tile: 256 out-cols x 8 out-rows, grid (8,128)=1024 blocks.
// 24B/pixel records split: uint4 A[] (classes 0..15) + uint2 B[] (16..18|fs).
// smem 55.5KB + <=64 regs -> 4 blocks/SM -> 32 warps (100% theoretical occ).
// ============================================================================
#define W_OUT 256
#define W_IN  288                  // + 2*RAD halo columns
#define HB    8                    // output rows per block
#define CHC_F 8                    // outputs per horizontal-slider task
#define STRIDE_A (W_IN * 4 + 4)    // 1156 words; %32==4 -> r*4 distinct banks
#define STRIDE_B (W_IN * 2 + 2)    // 578 words;  %32==2 -> 2r distinct banks
#define SMEM_WORDS (HB * (STRIDE_A + STRIDE_B))
#define SMEM_BYTES (SMEM_WORDS * 4)   // 55488 B

__device__ __forceinline__ void pk_add(unsigned long long& w0,
                                       unsigned long long& w1,
                                       unsigned& w2, int cls) {
    if (cls < 8)       w0 += 1ull << (cls * 8);
    else if (cls < 16) w1 += 1ull << ((cls & 7) * 8);
    else               w2 += 1u << ((cls - 16) * 8);
}
__device__ __forceinline__ void pk_sub(unsigned long long& w0,
                                       unsigned long long& w1,
                                       unsigned& w2, int cls) {
    if (cls < 8)       w0 -= 1ull << (cls * 8);
    else if (cls < 16) w1 -= 1ull << ((cls & 7) * 8);
    else               w2 -= 1u << ((cls - 16) * 8);
}

// unpack 4 bytes into two u32 halfword pairs
#define PLO(w) __byte_perm((w), 0, 0x4140)
#define PHI(w) __byte_perm((w), 0, 0x4342)

__device__ __forceinline__ void srec_add(const unsigned* __restrict__ smA,
                                         const unsigned* __restrict__ smB,
                                         int s, unsigned* h, float& fs) {
    uint4 a = *(const uint4*)(smA + s * 4);
    uint2 b = *(const uint2*)(smB + s * 2);
    h[0] += PLO(a.x); h[1] += PHI(a.x);
    h[2] += PLO(a.y); h[3] += PHI(a.y);
    h[4] += PLO(a.z); h[5] += PHI(a.z);
    h[6] += PLO(a.w); h[7] += PHI(a.w);
    h[8] += PLO(b.x); h[9] += PHI(b.x);
    fs += __uint_as_float(b.y);
}
__device__ __forceinline__ void srec_sub(const unsigned* __restrict__ smA,
                                         const unsigned* __restrict__ smB,
                                         int s, unsigned* h, float& fs) {
    uint4 a = *(const uint4*)(smA + s * 4);
    uint2 b = *(const uint2*)(smB + s * 2);
    h[0] -= PLO(a.x); h[1] -= PHI(a.x);
    h[2] -= PLO(a.y); h[3] -= PHI(a.y);
    h[4] -= PLO(a.z); h[5] -= PHI(a.z);
    h[6] -= PLO(a.w); h[7] -= PHI(a.w);
    h[8] -= PLO(b.x); h[9] -= PHI(b.x);
    fs -= __uint_as_float(b.y);
}

__global__ __launch_bounds__(256, 4) void fusedBC(float* __restrict__ out) {
    extern __shared__ unsigned sm[];
    unsigned* smA = sm;                          // HB * STRIDE_A words
    unsigned* smB = sm + HB * STRIDE_A;          // HB * STRIDE_B words
    const int x0 = blockIdx.x * W_OUT;
    const int y0 = blockIdx.y * HB;
    const int tid = threadIdx.x;

    // ---------------- Phase 1: vertical 33-tap sliders (288 cols, strided) --
    for (int j = tid; j < W_IN; j += 256) {
        int xg = x0 - RAD + j;
        bool valid = (xg >= 0) && (xg < WW);

        unsigned long long w0 = 0, w1 = 0;
        unsigned w2 = 0;
        float fs = 0.f;
        if (valid) {
#pragma unroll
            for (int yi = 0; yi < 33; yi++) {
                int y = y0 - RAD + yi;
                if (y >= 0 && y < HH) {
                    int idx = y * WW + xg;
                    fs += g_wpe[idx];
                    pk_add(w0, w1, w2, g_predict[idx]);
                }
            }
        }
#pragma unroll
        for (int r = 0; r < HB; r++) {
            *(uint4*)(smA + r * STRIDE_A + j * 4) =
                make_uint4((unsigned)w0, (unsigned)(w0 >> 32),
                           (unsigned)w1, (unsigned)(w1 >> 32));
            *(uint2*)(smB + r * STRIDE_B + j * 2) =
                make_uint2(w2, __float_as_uint(fs));
            if (valid) {
                int ya = y0 + r + RAD + 1;
                if (ya < HH) {
                    int ia = ya * WW + xg;
                    fs += g_wpe[ia];
                    pk_add(w0, w1, w2, g_predict[ia]);
                }
                int yr = y0 + r - RAD;
                if (yr >= 0) {
                    int ir = yr * WW + xg;
                    fs -= g_wpe[ir];
                    pk_sub(w0, w1, w2, g_predict[ir]);
                }
            }
        }
    }
    __syncthreads();

    // ---------------- Phase 2: horizontal 33-tap sliders (256 tasks) --------
    const int r = tid & 7;          // low bits -> conflict-free LDS phases
    const int c = tid >> 3;
    const int xo = x0 + c * CHC_F;
    const unsigned* rowA = smA + r * STRIDE_A;
    const unsigned* rowB = smB + r * STRIDE_B;

    int yy = y0 + r;
    int wy = min(yy + RAD, HH - 1) - max(yy - RAD, 0) + 1;

    unsigned h[10];
#pragma unroll
    for (int i = 0; i < 10; i++) h[i] = 0;
    float fs = 0.f;

#pragma unroll
    for (int si = 0; si < 33; si++)
        srec_add(rowA, rowB, c * CHC_F + si, h, fs);

#pragma unroll
    for (int k4 = 0; k4 < CHC_F / 4; k4++) {
        float s4[4], i4[4], u4[4];
#pragma unroll
        for (int kk = 0; kk < 4; kk++) {
            int k = k4 * 4 + kk;
            int x = xo + k;
            int wx = min(x + RAD, WW - 1) - max(x - RAD, 0) + 1;
            float fcount = (float)(wx * wy);    // exact window size
            float invc = __frcp_rn(fcount);
            float eps = 1e-6f * fcount;

            float acc0 = 0.f, acc1 = 0.f;       // two chains for ILP
#pragma unroll
            for (int p = 0; p < 10; p++) {
                float slo = (float)(h[p] & 0xFFFFu);
                float shi = (float)(h[p] >> 16);
                acc0 += slo * __logf(slo + eps);   // 0*log(eps) == 0
                if (p != 9)                         // lane 19 is zero pad
                    acc1 += shi * __logf(shi + eps);
            }
            float impurity = (__logf(fcount) - (acc0 + acc1) * invc)
                             * INV_LOG19;
            float unc = fs * invc;

            s4[kk] = impurity * unc;
            i4[kk] = impurity;
            u4[kk] = unc;

            if (k < CHC_F - 1) {
                srec_add(rowA, rowB, c * CHC_F + k + 33, h, fs);
                srec_sub(rowA, rowB, c * CHC_F + k, h, fs);
            }
        }
        int o = yy * WW + xo + k4 * 4;
        *(float4*)(out + o)            = make_float4(s4[0], s4[1], s4[2], s4[3]);
        *(float4*)(out + HWSZ + o)     = make_float4(i4[0], i4[1], i4[2], i4[3]);
        *(float4*)(out + 2 * HWSZ + o) = make_float4(u4[0], u4[1], u4[2], u4[3]);
    }
}

// ============================================================================
extern "C" void kernel_launch(void* const* d_in, const int* in_sizes, int n_in,
                              void* d_out, int out_size) {
    const float* logit = (const float*)d_in[0];
    const float* cw    = (const float*)d_in[1];
    float* out = (float*)d_out;

    cudaFuncSetAttribute(fusedBC, cudaFuncAttributeMaxDynamicSharedMemorySize,
                         SMEM_BYTES);

    passA<<<HWSZ / 256, 256>>>(logit, cw);
    fusedBC<<<dim3(WW / W_OUT, HH / HB), 256, SMEM_BYTES>>>(out);
}